// round 1
// baseline (speedup 1.0000x reference)
#include <cuda_runtime.h>

// LCC (local cross-correlation) over [B=2,1,192,192,192] fp32 volumes.
// Fully fused single pass: per-CTA (x,y) tile + z-sweep with register rings.
//  - z-box: register rings (raw planes k-1..k+1; product planes k-1..k+1)
//  - y-box: 4-row register strips per thread; strip boundaries via smem
//  - x-box: warp shuffles (lane == x)
// Replicate padding: raw clamping == replicate for the first box; for the
// second box (on products P) volume-edge neighbors select own P.

namespace {
constexpr int   NV    = 192;
constexpr int   NV2   = NV * NV;
constexpr long long NV3 = (long long)NV * NV * NV;
constexpr int   TOUT  = 28;   // output tile per block in x and y
constexpr int   BXT   = 32;   // threads in x (== covered columns incl halo2)
constexpr int   BYT   = 8;    // threads in y
constexpr int   RY    = 4;    // rows per thread (8*4 = 32 covered rows)
constexpr int   ZCHUNKS = 4;
constexpr int   ZC    = NV / ZCHUNKS;  // 48 output planes per CTA
constexpr float EPSV  = 1e-5f;
constexpr float INV27 = 1.0f / 27.0f;
}

__global__ void zero_out_kernel(float* out, int n) {
    int i = blockIdx.x * blockDim.x + threadIdx.x;
    if (i < n) out[i] = 0.0f;
}

__global__ __launch_bounds__(BXT * BYT)
void lcc_kernel(const float* __restrict__ gF,
                const float* __restrict__ gM,
                float* __restrict__ out)
{
    __shared__ float sA[32][33];   // z-summed F plane (y-boundary exchange)
    __shared__ float sB[32][33];   // z-summed M plane
    __shared__ float sP0[32][33];  // z-summed dF*dM
    __shared__ float sP1[32][33];  // z-summed dF*dF
    __shared__ float sP2[32][33];  // z-summed dM*dM
    __shared__ float wsum[BYT];

    const int tx  = threadIdx.x;
    const int ty  = threadIdx.y;
    const int yl0 = ty * RY;
    const int b   = blockIdx.z / ZCHUNKS;
    const int Z0  = (blockIdx.z % ZCHUNKS) * ZC;

    const int x_nom = (int)blockIdx.x * TOUT - 2 + tx;
    const int x_g   = min(max(x_nom, 0), NV - 1);

    int y_nom[RY];
    int yoff[RY];
#pragma unroll
    for (int i = 0; i < RY; i++) {
        y_nom[i] = (int)blockIdx.y * TOUT - 2 + yl0 + i;
        int yg   = min(max(y_nom[i], 0), NV - 1);
        yoff[i]  = yg * NV + x_g;
    }

    const float* F = gF + (long long)b * NV3;
    const float* M = gM + (long long)b * NV3;

    // register rings
    float rF0[RY], rF1[RY], rF2[RY];
    float rM0[RY], rM1[RY], rM2[RY];
    float pFM0[RY], pFM1[RY], pFM2[RY];
    float pFF0[RY], pFF1[RY], pFF2[RY];
    float pMM0[RY], pMM1[RY], pMM2[RY];
    float tFM[RY], tFF[RY], tMM[RY];
    float acc = 0.0f;

    const unsigned FULL = 0xffffffffu;

    auto load2 = [&](int z, float (&oF)[RY], float (&oM)[RY]) {
        const float* fp = F + (long long)z * NV2;
        const float* mp = M + (long long)z * NV2;
#pragma unroll
        for (int i = 0; i < RY; i++) {
            oF[i] = __ldg(fp + yoff[i]);
            oM[i] = __ldg(mp + yoff[i]);
        }
    };

    // Computes P(j) (products of mean-subtracted fields) for the plane whose
    // raw data sits in ring slot 1 (slots hold planes j-1, j, j+1). Results
    // valid for covered columns/rows with x_nom,y_nom in [0, NV-1].
    auto stepP = [&]() {
        float zf[RY], zm[RY];
#pragma unroll
        for (int i = 0; i < RY; i++) {
            zf[i] = rF0[i] + rF1[i] + rF2[i];
            zm[i] = rM0[i] + rM1[i] + rM2[i];
            sA[yl0 + i][tx] = zf[i];
            sB[yl0 + i][tx] = zm[i];
        }
        __syncthreads();
        const int rup = (yl0 > 0) ? (yl0 - 1) : 0;
        const int rdn = (yl0 + RY < 32) ? (yl0 + RY) : 31;
        float upF = sA[rup][tx], dnF = sA[rdn][tx];
        float upM = sB[rup][tx], dnM = sB[rdn][tx];
        float yf[RY], ym[RY];
        yf[0] = upF  + zf[0] + zf[1];  ym[0] = upM  + zm[0] + zm[1];
        yf[1] = zf[0] + zf[1] + zf[2]; ym[1] = zm[0] + zm[1] + zm[2];
        yf[2] = zf[1] + zf[2] + zf[3]; ym[2] = zm[1] + zm[2] + zm[3];
        yf[3] = zf[2] + zf[3] + dnF;   ym[3] = zm[2] + zm[3] + dnM;
        __syncthreads();  // guards sA/sB reuse next call
#pragma unroll
        for (int i = 0; i < RY; i++) {
            float lF = __shfl_up_sync(FULL, yf[i], 1);
            float rFs = __shfl_down_sync(FULL, yf[i], 1);
            float lM = __shfl_up_sync(FULL, ym[i], 1);
            float rMs = __shfl_down_sync(FULL, ym[i], 1);
            float uF = (lF + yf[i] + rFs) * INV27;
            float uM = (lM + ym[i] + rMs) * INV27;
            float dF = rF1[i] - uF;
            float dM = rM1[i] - uM;
            tFM[i] = dF * dM;
            tFF[i] = dF * dF;
            tMM[i] = dM * dM;
        }
    };

    // ---- Prologue: fill P ring so slots (1,2) hold P(Z0-1), P(Z0) ----
    if (Z0 == 0) {
        load2(0, rF0, rM0);
#pragma unroll
        for (int i = 0; i < RY; i++) { rF1[i] = rF0[i]; rM1[i] = rM0[i]; }
        load2(1, rF2, rM2);
        stepP();  // P(0); P(-1) replicates P(0)
#pragma unroll
        for (int i = 0; i < RY; i++) {
            pFM1[i] = tFM[i]; pFF1[i] = tFF[i]; pMM1[i] = tMM[i];
            pFM2[i] = tFM[i]; pFF2[i] = tFF[i]; pMM2[i] = tMM[i];
        }
    } else {
        load2(Z0 - 2, rF0, rM0);
        load2(Z0 - 1, rF1, rM1);
        load2(Z0,     rF2, rM2);
        stepP();  // P(Z0-1)
#pragma unroll
        for (int i = 0; i < RY; i++) {
            pFM1[i] = tFM[i]; pFF1[i] = tFF[i]; pMM1[i] = tMM[i];
        }
#pragma unroll
        for (int i = 0; i < RY; i++) {
            rF0[i] = rF1[i]; rF1[i] = rF2[i];
            rM0[i] = rM1[i]; rM1[i] = rM2[i];
        }
        load2(Z0 + 1, rF2, rM2);
        stepP();  // P(Z0)
#pragma unroll
        for (int i = 0; i < RY; i++) {
            pFM2[i] = tFM[i]; pFF2[i] = tFF[i]; pMM2[i] = tMM[i];
        }
    }

    const bool lane_ok = (tx >= 2) && (tx < 2 + TOUT) && (x_nom < NV);

    // ---- Main z sweep ----
    for (int k = Z0; k < Z0 + ZC; ++k) {
        // shift P ring: after this, slots (0,1) = P(k-1), P(k)
#pragma unroll
        for (int i = 0; i < RY; i++) {
            pFM0[i] = pFM1[i]; pFF0[i] = pFF1[i]; pMM0[i] = pMM1[i];
            pFM1[i] = pFM2[i]; pFF1[i] = pFF2[i]; pMM1[i] = pMM2[i];
        }
        if (k + 1 < NV) {
#pragma unroll
            for (int i = 0; i < RY; i++) {
                rF0[i] = rF1[i]; rF1[i] = rF2[i];
                rM0[i] = rM1[i]; rM1[i] = rM2[i];
            }
            const int zl = (k + 2 < NV) ? (k + 2) : (NV - 1);
            load2(zl, rF2, rM2);
            stepP();  // P(k+1)
#pragma unroll
            for (int i = 0; i < RY; i++) {
                pFM2[i] = tFM[i]; pFF2[i] = tFF[i]; pMM2[i] = tMM[i];
            }
        } else {
            // P(k+1) replicates P(NV-1): slot 2 already holds it.
            __syncthreads();  // guard sP reuse below vs previous iteration reads
        }

        // ---- cross/var box over P, then z-score ----
        float zpA[RY], zpB[RY], zpC[RY];
#pragma unroll
        for (int i = 0; i < RY; i++) {
            zpA[i] = pFM0[i] + pFM1[i] + pFM2[i];
            zpB[i] = pFF0[i] + pFF1[i] + pFF2[i];
            zpC[i] = pMM0[i] + pMM1[i] + pMM2[i];
            sP0[yl0 + i][tx] = zpA[i];
            sP1[yl0 + i][tx] = zpB[i];
            sP2[yl0 + i][tx] = zpC[i];
        }
        __syncthreads();
        const int rup = (yl0 > 0) ? (yl0 - 1) : 0;
        const int rdn = (yl0 + RY < 32) ? (yl0 + RY) : 31;
        float upA = sP0[rup][tx], dnA = sP0[rdn][tx];
        float upB = sP1[rup][tx], dnB = sP1[rdn][tx];
        float upC = sP2[rup][tx], dnC = sP2[rdn][tx];
#pragma unroll
        for (int i = 0; i < RY; i++) {
            float pvA = (i > 0) ? zpA[i - 1] : upA;
            float pvB = (i > 0) ? zpB[i - 1] : upB;
            float pvC = (i > 0) ? zpC[i - 1] : upC;
            float nxA = (i < RY - 1) ? zpA[i + 1] : dnA;
            float nxB = (i < RY - 1) ? zpB[i + 1] : dnB;
            float nxC = (i < RY - 1) ? zpC[i + 1] : dnC;
            // volume-edge replicate of P (select own value)
            pvA = (y_nom[i] == 0) ? zpA[i] : pvA;
            pvB = (y_nom[i] == 0) ? zpB[i] : pvB;
            pvC = (y_nom[i] == 0) ? zpC[i] : pvC;
            nxA = (y_nom[i] == NV - 1) ? zpA[i] : nxA;
            nxB = (y_nom[i] == NV - 1) ? zpB[i] : nxB;
            nxC = (y_nom[i] == NV - 1) ? zpC[i] : nxC;
            float ybA = pvA + zpA[i] + nxA;
            float ybB = pvB + zpB[i] + nxB;
            float ybC = pvC + zpC[i] + nxC;
            float lA = __shfl_up_sync(FULL, ybA, 1);
            float rA = __shfl_down_sync(FULL, ybA, 1);
            float lB = __shfl_up_sync(FULL, ybB, 1);
            float rB = __shfl_down_sync(FULL, ybB, 1);
            float lC = __shfl_up_sync(FULL, ybC, 1);
            float rC = __shfl_down_sync(FULL, ybC, 1);
            lA = (x_nom == 0) ? ybA : lA;
            lB = (x_nom == 0) ? ybB : lB;
            lC = (x_nom == 0) ? ybC : lC;
            rA = (x_nom == NV - 1) ? ybA : rA;
            rB = (x_nom == NV - 1) ? ybB : rB;
            rC = (x_nom == NV - 1) ? ybC : rC;
            float cr = lA + ybA + rA;
            float vf = lB + ybB + rB;
            float vm = lC + ybC + rC;
            float z  = __fdividef(cr * cr, vf * vm + EPSV);
            const int yloc = yl0 + i;
            if (lane_ok && yloc >= 2 && yloc < 2 + TOUT && y_nom[i] < NV)
                acc += z;
        }
        __syncthreads();  // guard sP reuse on next iteration
    }

    // ---- Reduction: warp -> block -> atomic ----
#pragma unroll
    for (int o = 16; o > 0; o >>= 1)
        acc += __shfl_xor_sync(FULL, acc, o);
    if (tx == 0) wsum[ty] = acc;
    __syncthreads();
    if (tx == 0 && ty == 0) {
        float t = 0.0f;
#pragma unroll
        for (int i = 0; i < BYT; i++) t += wsum[i];
        atomicAdd(&out[b], t * (-1.0f / (float)NV3));
    }
}

extern "C" void kernel_launch(void* const* d_in, const int* in_sizes, int n_in,
                              void* d_out, int out_size) {
    const float* F = (const float*)d_in[0];
    const float* M = (const float*)d_in[1];
    float* out = (float*)d_out;

    const int B = (int)(in_sizes[0] / (NV * (long long)NV * NV));

    zero_out_kernel<<<1, 32>>>(out, out_size);

    dim3 block(BXT, BYT, 1);
    dim3 grid((NV + TOUT - 1) / TOUT, (NV + TOUT - 1) / TOUT, B * ZCHUNKS);
    lcc_kernel<<<grid, block>>>(F, M, out);
}

// round 2
// speedup vs baseline: 1.5072x; 1.5072x over previous
#include <cuda_runtime.h>

// LCC over [B=2,1,192,192,192] fp32. Fully fused z-sweep.
// Round-2: RY=2 (64-reg budget, 4 CTAs/SM), one-iteration load prefetch,
// parity double-buffered smem (2 barriers/plane instead of 4).

namespace {
constexpr int   NV    = 192;
constexpr int   NV2   = NV * NV;
constexpr long long NV3 = (long long)NV * NV2;
constexpr int   BXT   = 32;   // lanes = x (30 usable, 28 outputs)
constexpr int   BYT   = 8;
constexpr int   RY    = 2;    // rows per thread
constexpr int   COVY  = BYT * RY;      // 16 covered rows
constexpr int   TOUTX = 28;
constexpr int   TOUTY = COVY - 4;      // 12 output rows
constexpr int   ZCHUNKS = 8;
constexpr int   ZC    = NV / ZCHUNKS;  // 24 output planes per CTA
constexpr float EPSV  = 1e-5f;
constexpr float INV27 = 1.0f / 27.0f;
constexpr unsigned FULL = 0xffffffffu;
}

__global__ void zero_out_kernel(float* out, int n) {
    int i = blockIdx.x * blockDim.x + threadIdx.x;
    if (i < n) out[i] = 0.0f;
}

__global__ __launch_bounds__(BXT * BYT, 4)
void lcc_kernel(const float* __restrict__ gF,
                const float* __restrict__ gM,
                float* __restrict__ out)
{
    __shared__ float sA [2][COVY][33];
    __shared__ float sB [2][COVY][33];
    __shared__ float sP0[2][COVY][33];
    __shared__ float sP1[2][COVY][33];
    __shared__ float sP2[2][COVY][33];
    __shared__ float wsum[BYT];

    const int tx  = threadIdx.x;
    const int ty  = threadIdx.y;
    const int yl0 = ty * RY;
    const int b   = blockIdx.z / ZCHUNKS;
    const int Z0  = (blockIdx.z % ZCHUNKS) * ZC;

    const int x_nom = (int)blockIdx.x * TOUTX - 2 + tx;
    const int x_g   = min(max(x_nom, 0), NV - 1);
    const int y_nom0 = (int)blockIdx.y * TOUTY - 2 + yl0;

    int yoff[RY];
#pragma unroll
    for (int i = 0; i < RY; i++) {
        int yg  = min(max(y_nom0 + i, 0), NV - 1);
        yoff[i] = yg * NV + x_g;
    }

    const float* F = gF + (long long)b * NV3;
    const float* M = gM + (long long)b * NV3;

    // raw z-ring, prefetch, P prev/curr/next
    float rF0[RY], rF1[RY], rF2[RY];
    float rM0[RY], rM1[RY], rM2[RY];
    float pfF[RY], pfM[RY];
    float vA[RY], vB[RY], vC[RY];   // P(k-1)
    float cA[RY], cB[RY], cC[RY];   // P(k)
    float nA[RY], nB[RY], nC[RY];   // P(k+1)
    float acc = 0.0f;

    auto load2 = [&](int z, float (&oF)[RY], float (&oM)[RY]) {
        const float* fp = F + (long long)z * NV2;
        const float* mp = M + (long long)z * NV2;
#pragma unroll
        for (int i = 0; i < RY; i++) {
            oF[i] = __ldg(fp + yoff[i]);
            oM[i] = __ldg(mp + yoff[i]);
        }
    };

    // P for the plane in ring slot 1 (ring holds j-1, j, j+1).
    auto stepP = [&](int par) {
        float zf[RY], zm[RY];
#pragma unroll
        for (int i = 0; i < RY; i++) {
            zf[i] = rF0[i] + rF1[i] + rF2[i];
            zm[i] = rM0[i] + rM1[i] + rM2[i];
            sA[par][yl0 + i][tx] = zf[i];
            sB[par][yl0 + i][tx] = zm[i];
        }
        __syncthreads();
        const int rup = yl0 ? yl0 - 1 : 0;
        const int rdn = (yl0 + RY < COVY) ? yl0 + RY : COVY - 1;
        float upF = sA[par][rup][tx], dnF = sA[par][rdn][tx];
        float upM = sB[par][rup][tx], dnM = sB[par][rdn][tx];
        float yf[RY], ym[RY];
        yf[0] = upF  + zf[0] + zf[1];  ym[0] = upM  + zm[0] + zm[1];
        yf[1] = zf[0] + zf[1] + dnF;   ym[1] = zm[0] + zm[1] + dnM;
#pragma unroll
        for (int i = 0; i < RY; i++) {
            float lF = __shfl_up_sync(FULL, yf[i], 1);
            float rR = __shfl_down_sync(FULL, yf[i], 1);
            float lM = __shfl_up_sync(FULL, ym[i], 1);
            float rS = __shfl_down_sync(FULL, ym[i], 1);
            float uF = (lF + yf[i] + rR) * INV27;
            float uM = (lM + ym[i] + rS) * INV27;
            float dF = rF1[i] - uF;
            float dM = rM1[i] - uM;
            nA[i] = dF * dM;
            nB[i] = dF * dF;
            nC[i] = dM * dM;
        }
    };

    // ---- Prologue ----
    if (Z0 == 0) {
        load2(0, rF0, rM0);
#pragma unroll
        for (int i = 0; i < RY; i++) { rF1[i] = rF0[i]; rM1[i] = rM0[i]; }
        load2(1, rF2, rM2);
        stepP(0);  // P(0); P(-1) replicates it
#pragma unroll
        for (int i = 0; i < RY; i++) {
            cA[i] = nA[i]; cB[i] = nB[i]; cC[i] = nC[i];
            vA[i] = nA[i]; vB[i] = nB[i]; vC[i] = nC[i];
        }
        load2(2, pfF, pfM);
    } else {
        load2(Z0 - 2, rF0, rM0);
        load2(Z0 - 1, rF1, rM1);
        load2(Z0,     rF2, rM2);
        stepP(0);  // P(Z0-1)
#pragma unroll
        for (int i = 0; i < RY; i++) { vA[i] = nA[i]; vB[i] = nB[i]; vC[i] = nC[i]; }
#pragma unroll
        for (int i = 0; i < RY; i++) {
            rF0[i] = rF1[i]; rF1[i] = rF2[i];
            rM0[i] = rM1[i]; rM1[i] = rM2[i];
        }
        load2(Z0 + 1, rF2, rM2);
        stepP(1);  // P(Z0)
#pragma unroll
        for (int i = 0; i < RY; i++) { cA[i] = nA[i]; cB[i] = nB[i]; cC[i] = nC[i]; }
        load2(Z0 + 2, pfF, pfM);
    }
    __syncthreads();  // separate prologue smem reads from loop writes

    const bool lane_ok = (tx >= 2) && (tx < 2 + TOUTX) && (x_nom < NV);
    bool rowok[RY];
#pragma unroll
    for (int i = 0; i < RY; i++) {
        int yloc = yl0 + i;
        rowok[i] = (yloc >= 2) && (yloc < 2 + TOUTY);
    }

    // ---- Main z sweep ----
    for (int k = Z0; k < Z0 + ZC; ++k) {
        const int par = (k - Z0) & 1;

        // consume prefetch (plane k+2) into ring, then issue plane k+3 loads
#pragma unroll
        for (int i = 0; i < RY; i++) {
            rF0[i] = rF1[i]; rF1[i] = rF2[i]; rF2[i] = pfF[i];
            rM0[i] = rM1[i]; rM1[i] = rM2[i]; rM2[i] = pfM[i];
        }
        {
            const int zl = min(k + 3, NV - 1);
            load2(zl, pfF, pfM);
        }

        if (k + 1 < NV) {
            stepP(par);               // n = P(k+1)
        } else {
#pragma unroll
            for (int i = 0; i < RY; i++) {  // replicate P(NV-1)
                nA[i] = cA[i]; nB[i] = cB[i]; nC[i] = cC[i];
            }
        }

        // ---- second box over P + z-score ----
        float zpA[RY], zpB[RY], zpC[RY];
#pragma unroll
        for (int i = 0; i < RY; i++) {
            zpA[i] = vA[i] + cA[i] + nA[i];
            zpB[i] = vB[i] + cB[i] + nB[i];
            zpC[i] = vC[i] + cC[i] + nC[i];
            sP0[par][yl0 + i][tx] = zpA[i];
            sP1[par][yl0 + i][tx] = zpB[i];
            sP2[par][yl0 + i][tx] = zpC[i];
        }
        __syncthreads();
        const int rup = yl0 ? yl0 - 1 : 0;
        const int rdn = (yl0 + RY < COVY) ? yl0 + RY : COVY - 1;
        float upA = sP0[par][rup][tx], dnA = sP0[par][rdn][tx];
        float upB = sP1[par][rup][tx], dnB = sP1[par][rdn][tx];
        float upC = sP2[par][rup][tx], dnC = sP2[par][rdn][tx];
#pragma unroll
        for (int i = 0; i < RY; i++) {
            float pvA = i ? zpA[0] : upA;
            float pvB = i ? zpB[0] : upB;
            float pvC = i ? zpC[0] : upC;
            float nxA = i ? dnA : zpA[1];
            float nxB = i ? dnB : zpB[1];
            float nxC = i ? dnC : zpC[1];
            const int y_nom = y_nom0 + i;
            pvA = (y_nom == 0) ? zpA[i] : pvA;
            pvB = (y_nom == 0) ? zpB[i] : pvB;
            pvC = (y_nom == 0) ? zpC[i] : pvC;
            nxA = (y_nom == NV - 1) ? zpA[i] : nxA;
            nxB = (y_nom == NV - 1) ? zpB[i] : nxB;
            nxC = (y_nom == NV - 1) ? zpC[i] : nxC;
            float ybA = pvA + zpA[i] + nxA;
            float ybB = pvB + zpB[i] + nxB;
            float ybC = pvC + zpC[i] + nxC;
            float lA = __shfl_up_sync(FULL, ybA, 1);
            float rA = __shfl_down_sync(FULL, ybA, 1);
            float lB = __shfl_up_sync(FULL, ybB, 1);
            float rB = __shfl_down_sync(FULL, ybB, 1);
            float lC = __shfl_up_sync(FULL, ybC, 1);
            float rC = __shfl_down_sync(FULL, ybC, 1);
            lA = (x_nom == 0) ? ybA : lA;
            lB = (x_nom == 0) ? ybB : lB;
            lC = (x_nom == 0) ? ybC : lC;
            rA = (x_nom == NV - 1) ? ybA : rA;
            rB = (x_nom == NV - 1) ? ybB : rB;
            rC = (x_nom == NV - 1) ? ybC : rC;
            float cr = lA + ybA + rA;
            float vf = lB + ybB + rB;
            float vm = lC + ybC + rC;
            float z  = __fdividef(cr * cr, vf * vm + EPSV);
            if (lane_ok && rowok[i])
                acc += z;
        }

        // rotate P prev/curr
#pragma unroll
        for (int i = 0; i < RY; i++) {
            vA[i] = cA[i]; vB[i] = cB[i]; vC[i] = cC[i];
            cA[i] = nA[i]; cB[i] = nB[i]; cC[i] = nC[i];
        }
    }

    // ---- Reduction ----
#pragma unroll
    for (int o = 16; o > 0; o >>= 1)
        acc += __shfl_xor_sync(FULL, acc, o);
    if (tx == 0) wsum[ty] = acc;
    __syncthreads();
    if (tx == 0 && ty == 0) {
        float t = 0.0f;
#pragma unroll
        for (int i = 0; i < BYT; i++) t += wsum[i];
        atomicAdd(&out[b], t * (-1.0f / (float)NV3));
    }
}

extern "C" void kernel_launch(void* const* d_in, const int* in_sizes, int n_in,
                              void* d_out, int out_size) {
    const float* F = (const float*)d_in[0];
    const float* M = (const float*)d_in[1];
    float* out = (float*)d_out;

    const int B = (int)(in_sizes[0] / (long long)NV3);

    zero_out_kernel<<<1, 32>>>(out, out_size);

    dim3 block(BXT, BYT, 1);
    dim3 grid((NV + TOUTX - 1) / TOUTX, NV / TOUTY, B * ZCHUNKS);
    lcc_kernel<<<grid, block>>>(F, M, out);
}

// round 3
// speedup vs baseline: 1.6299x; 1.0814x over previous
#include <cuda_runtime.h>

// LCC over [B=2,1,192,192,192] fp32, fully fused z-sweep.
// Round-3: float2 x-vectorization (half the SHFL/LDS/STS per voxel),
// packed f32x2 arithmetic, in-iteration load pipelining, unroll-3 ring
// rotation (no register shifts).

namespace {
constexpr int NV   = 192;
constexpr int NV2  = NV * NV;
constexpr long long NV3 = (long long)NV * NV2;
constexpr int BYT  = 8;
constexpr int RY   = 2;
constexpr int COVY = BYT * RY;      // 16 covered rows
constexpr int TOUTX = 48;           // outputs/block in x (lanes cover 64)
constexpr int TOUTY = COVY - 4;     // 12 outputs/block in y
constexpr int ZCHUNKS = 8;
constexpr int ZC   = NV / ZCHUNKS;  // 24 output planes per CTA
constexpr float EPSV  = 1e-5f;
constexpr float INV27 = 1.0f / 27.0f;
constexpr unsigned FULL = 0xffffffffu;
}

__device__ __forceinline__ float2 a2(float2 a, float2 b) {
    float2 r;
    asm("{.reg .b64 ra,rb,rc;\n\t"
        "mov.b64 ra,{%2,%3};\n\t"
        "mov.b64 rb,{%4,%5};\n\t"
        "add.rn.f32x2 rc,ra,rb;\n\t"
        "mov.b64 {%0,%1},rc;}\n\t"
        : "=f"(r.x), "=f"(r.y)
        : "f"(a.x), "f"(a.y), "f"(b.x), "f"(b.y));
    return r;
}
__device__ __forceinline__ float2 m2(float2 a, float2 b) {
    float2 r;
    asm("{.reg .b64 ra,rb,rc;\n\t"
        "mov.b64 ra,{%2,%3};\n\t"
        "mov.b64 rb,{%4,%5};\n\t"
        "mul.rn.f32x2 rc,ra,rb;\n\t"
        "mov.b64 {%0,%1},rc;}\n\t"
        : "=f"(r.x), "=f"(r.y)
        : "f"(a.x), "f"(a.y), "f"(b.x), "f"(b.y));
    return r;
}
__device__ __forceinline__ float2 f2ma(float2 a, float2 b, float2 c) {
    float2 r;
    asm("{.reg .b64 ra,rb,rc,rd;\n\t"
        "mov.b64 ra,{%2,%3};\n\t"
        "mov.b64 rb,{%4,%5};\n\t"
        "mov.b64 rc,{%6,%7};\n\t"
        "fma.rn.f32x2 rd,ra,rb,rc;\n\t"
        "mov.b64 {%0,%1},rd;}\n\t"
        : "=f"(r.x), "=f"(r.y)
        : "f"(a.x), "f"(a.y), "f"(b.x), "f"(b.y), "f"(c.x), "f"(c.y));
    return r;
}

__global__ void zero_out_kernel(float* out, int n) {
    int i = blockIdx.x * blockDim.x + threadIdx.x;
    if (i < n) out[i] = 0.0f;
}

__global__ __launch_bounds__(256, 3)
void lcc_kernel(const float* __restrict__ gF,
                const float* __restrict__ gM,
                float* __restrict__ out)
{
    __shared__ float2 sA [2][COVY][33];
    __shared__ float2 sB [2][COVY][33];
    __shared__ float2 sQ0[2][COVY][33];
    __shared__ float2 sQ1[2][COVY][33];
    __shared__ float2 sQ2[2][COVY][33];
    __shared__ float  wsum[BYT];

    const int tx  = threadIdx.x;
    const int ty  = threadIdx.y;
    const int yl0 = ty * RY;
    const int b   = blockIdx.z / ZCHUNKS;
    const int Z0  = (blockIdx.z % ZCHUNKS) * ZC;

    const int x_nom0 = (int)blockIdx.x * TOUTX - 2 + 2 * tx;   // even
    const int xbase  = min(max(x_nom0, 0), NV - 2);
    const bool fixlo  = (x_nom0 < 0);
    const bool fixhi  = (x_nom0 > NV - 2);
    const bool fixXlo = (x_nom0 == 0);          // component .x at x==0
    const bool fixXhi = (x_nom0 + 1 == NV - 1); // component .y at x==191

    const int y_nom0 = (int)blockIdx.y * TOUTY - 2 + yl0;
    const bool fixYup = (y_nom0 == 0);          // row0's up at volume top
    const bool fixYdn = (y_nom0 + 1 == NV - 1); // row1's down at volume bottom

    int yoff[RY];
#pragma unroll
    for (int i = 0; i < RY; i++)
        yoff[i] = min(max(y_nom0 + i, 0), NV - 1) * NV;

    const float* F = gF + (long long)b * NV3;
    const float* M = gM + (long long)b * NV3;

    float2 rF[3][RY], rM[3][RY];               // raw plane ring
    float2 pA[3][RY], pB[3][RY], pC[3][RY];    // P plane ring (FM, FF, MM)
    float2 acc = make_float2(0.f, 0.f);
    int sp = 0, bp = 0;

    const float2 NEGI = make_float2(-INV27, -INV27);
    const float2 EPS2 = make_float2(EPSV, EPSV);

    const bool okl = (tx >= 1 && tx <= 24);
    float2 maskp[RY];
#pragma unroll
    for (int i = 0; i < RY; i++) {
        int yloc = yl0 + i;
        float m = (okl && yloc >= 2 && yloc < 2 + TOUTY) ? 1.0f : 0.0f;
        maskp[i] = make_float2(m, m);
    }

    auto loadp = [&](int z, float2 (&oF)[RY], float2 (&oM)[RY]) {
        z = min(max(z, 0), NV - 1);
        const float* fp = F + z * NV2;
        const float* mp = M + z * NV2;
#pragma unroll
        for (int i = 0; i < RY; i++) {
            float2 vF = __ldg(reinterpret_cast<const float2*>(fp + yoff[i] + xbase));
            float2 vM = __ldg(reinterpret_cast<const float2*>(mp + yoff[i] + xbase));
            oF[i].x = fixhi ? vF.y : vF.x;  oF[i].y = fixlo ? vF.x : vF.y;
            oM[i].x = fixhi ? vM.y : vM.x;  oM[i].y = fixlo ? vM.x : vM.y;
        }
    };

    const int rup = yl0 ? yl0 - 1 : 0;
    const int rdn = (yl0 + RY < COVY) ? yl0 + RY : COVY - 1;

    // P for the plane in raw slot ic (ip,ic,in_ = planes j-1, j, j+1); write slot iw.
    auto stepP = [&](int ip, int ic, int in_, int iw) {
        float2 zf[RY], zm[RY];
#pragma unroll
        for (int i = 0; i < RY; i++) {
            zf[i] = a2(a2(rF[ip][i], rF[ic][i]), rF[in_][i]);
            zm[i] = a2(a2(rM[ip][i], rM[ic][i]), rM[in_][i]);
            sA[sp][yl0 + i][tx] = zf[i];
            sB[sp][yl0 + i][tx] = zm[i];
        }
        __syncthreads();
        float2 upF = sA[sp][rup][tx], dnF = sA[sp][rdn][tx];
        float2 upM = sB[sp][rup][tx], dnM = sB[sp][rdn][tx];
        float2 yf[RY], ym[RY];
        yf[0] = a2(a2(upF, zf[0]), zf[1]);  yf[1] = a2(a2(zf[0], zf[1]), dnF);
        ym[0] = a2(a2(upM, zm[0]), zm[1]);  ym[1] = a2(a2(zm[0], zm[1]), dnM);
#pragma unroll
        for (int i = 0; i < RY; i++) {
            float lF = __shfl_up_sync(FULL, yf[i].y, 1);
            float rG = __shfl_down_sync(FULL, yf[i].x, 1);
            float pF = yf[i].x + yf[i].y;
            float2 sF = make_float2(lF + pF, pF + rG);
            float lM = __shfl_up_sync(FULL, ym[i].y, 1);
            float rH = __shfl_down_sync(FULL, ym[i].x, 1);
            float pM = ym[i].x + ym[i].y;
            float2 sM = make_float2(lM + pM, pM + rH);
            float2 dF = f2ma(sF, NEGI, rF[ic][i]);
            float2 dM = f2ma(sM, NEGI, rM[ic][i]);
            pA[iw][i] = m2(dF, dM);
            pB[iw][i] = m2(dF, dF);
            pC[iw][i] = m2(dM, dM);
        }
        sp ^= 1;
    };

    // second box over P slots (i0,i1,i2) = P(j-1),P(j),P(j+1); accumulate plane j.
    auto box2 = [&](int i0, int i1, int i2) {
        float2 zA[RY], zB[RY], zD[RY];
#pragma unroll
        for (int i = 0; i < RY; i++) {
            zA[i] = a2(a2(pA[i0][i], pA[i1][i]), pA[i2][i]);
            zB[i] = a2(a2(pB[i0][i], pB[i1][i]), pB[i2][i]);
            zD[i] = a2(a2(pC[i0][i], pC[i1][i]), pC[i2][i]);
            sQ0[bp][yl0 + i][tx] = zA[i];
            sQ1[bp][yl0 + i][tx] = zB[i];
            sQ2[bp][yl0 + i][tx] = zD[i];
        }
        __syncthreads();
        float2 uA = sQ0[bp][rup][tx], dA = sQ0[bp][rdn][tx];
        float2 uB = sQ1[bp][rup][tx], dB = sQ1[bp][rdn][tx];
        float2 uD = sQ2[bp][rup][tx], dD = sQ2[bp][rdn][tx];
        // replicate-P at volume top/bottom
        uA = fixYup ? zA[0] : uA;  dA = fixYdn ? zA[1] : dA;
        uB = fixYup ? zB[0] : uB;  dB = fixYdn ? zB[1] : dB;
        uD = fixYup ? zD[0] : uD;  dD = fixYdn ? zD[1] : dD;
        float2 ybA[RY], ybB[RY], ybD[RY];
        ybA[0] = a2(a2(uA, zA[0]), zA[1]);  ybA[1] = a2(a2(zA[0], zA[1]), dA);
        ybB[0] = a2(a2(uB, zB[0]), zB[1]);  ybB[1] = a2(a2(zB[0], zB[1]), dB);
        ybD[0] = a2(a2(uD, zD[0]), zD[1]);  ybD[1] = a2(a2(zD[0], zD[1]), dD);
#pragma unroll
        for (int i = 0; i < RY; i++) {
            float lA = __shfl_up_sync(FULL, ybA[i].y, 1);
            float rA = __shfl_down_sync(FULL, ybA[i].x, 1);
            float pA_ = ybA[i].x + ybA[i].y;
            float2 crA = make_float2((fixXlo ? ybA[i].x : lA) + pA_,
                                     pA_ + (fixXhi ? ybA[i].y : rA));
            float lB = __shfl_up_sync(FULL, ybB[i].y, 1);
            float rB = __shfl_down_sync(FULL, ybB[i].x, 1);
            float pB_ = ybB[i].x + ybB[i].y;
            float2 crB = make_float2((fixXlo ? ybB[i].x : lB) + pB_,
                                     pB_ + (fixXhi ? ybB[i].y : rB));
            float lD = __shfl_up_sync(FULL, ybD[i].y, 1);
            float rD = __shfl_down_sync(FULL, ybD[i].x, 1);
            float pD_ = ybD[i].x + ybD[i].y;
            float2 crD = make_float2((fixXlo ? ybD[i].x : lD) + pD_,
                                     pD_ + (fixXhi ? ybD[i].y : rD));
            float2 num = m2(crA, crA);
            float2 den = f2ma(crB, crD, EPS2);
            float2 zv  = make_float2(__fdividef(num.x, den.x),
                                     __fdividef(num.y, den.y));
            acc = f2ma(zv, maskp[i], acc);
        }
        bp ^= 1;
    };

    // ---- Prologue: establish P(Z0-1),P(Z0),P(Z0+1) in P[0..2]; raw[0]=Z0+1, raw[1]=Z0+2 ----
    if (Z0 == 0) {
        loadp(0, rF[2], rM[2]);
        loadp(1, rF[0], rM[0]);
#pragma unroll
        for (int i = 0; i < RY; i++) { rF[1][i] = rF[2][i]; rM[1][i] = rM[2][i]; }
        stepP(1, 2, 0, 1);   // P(0) -> P[1]
#pragma unroll
        for (int i = 0; i < RY; i++) {   // P(-1) := P(0)
            pA[0][i] = pA[1][i]; pB[0][i] = pB[1][i]; pC[0][i] = pC[1][i];
        }
        loadp(2, rF[1], rM[1]);
        stepP(2, 0, 1, 2);   // P(1) -> P[2]
    } else {
        loadp(Z0 - 2, rF[0], rM[0]);
        loadp(Z0 - 1, rF[1], rM[1]);
        loadp(Z0,     rF[2], rM[2]);
        stepP(0, 1, 2, 0);   // P(Z0-1)
        loadp(Z0 + 1, rF[0], rM[0]);
        stepP(1, 2, 0, 1);   // P(Z0)
        loadp(Z0 + 2, rF[1], rM[1]);
        stepP(2, 0, 1, 2);   // P(Z0+1)
    }

    // ---- Main z sweep, unrolled by 3 with static ring rotation ----
    auto body = [&](int j, int s0, int s1, int s2) {
        loadp(j + 3, rF[s2], rM[s2]);   // overwrite oldest raw slot (clamped)
        box2(s0, s1, s2);               // output plane j
        if (j != Z0 + ZC - 1) {
            if (j + 2 < NV) {
                stepP(s0, s1, s2, s0);  // P(j+2) -> oldest P slot
            } else {
#pragma unroll
                for (int i = 0; i < RY; i++) {  // P(j+2) := P(NV-1)
                    pA[s0][i] = pA[s2][i];
                    pB[s0][i] = pB[s2][i];
                    pC[s0][i] = pC[s2][i];
                }
            }
        }
    };
    for (int kb = 0; kb < ZC; kb += 3) {
        body(Z0 + kb,     0, 1, 2);
        body(Z0 + kb + 1, 1, 2, 0);
        body(Z0 + kb + 2, 2, 0, 1);
    }

    // ---- Reduction ----
    float t = acc.x + acc.y;
#pragma unroll
    for (int o = 16; o > 0; o >>= 1)
        t += __shfl_xor_sync(FULL, t, o);
    if (tx == 0) wsum[ty] = t;
    __syncthreads();
    if (tx == 0 && ty == 0) {
        float s = 0.0f;
#pragma unroll
        for (int i = 0; i < BYT; i++) s += wsum[i];
        atomicAdd(&out[b], s * (-1.0f / (float)NV3));
    }
}

extern "C" void kernel_launch(void* const* d_in, const int* in_sizes, int n_in,
                              void* d_out, int out_size) {
    const float* F = (const float*)d_in[0];
    const float* M = (const float*)d_in[1];
    float* out = (float*)d_out;

    const int B = (int)(in_sizes[0] / (long long)NV3);

    zero_out_kernel<<<1, 32>>>(out, out_size);

    dim3 block(32, BYT, 1);
    dim3 grid(NV / TOUTX, NV / TOUTY, B * ZCHUNKS);
    lcc_kernel<<<grid, block>>>(F, M, out);
}